// round 10
// baseline (speedup 1.0000x reference)
#include <cuda_runtime.h>
#include <cuda_fp16.h>
#include <cstdint>

#define NN 65536
#define NE 1048576
#define DFEAT 64

// Scratch (device globals — allocation is forbidden)
__device__ int   g_count[NN];
__device__ int   g_offset[NN + 1];
__device__ int   g_cursor[NN];
__device__ int2  g_ecv[NE];          // row-grouped (col, val_bits)
__device__ uint2 g_xh[NN * 16];      // fp16 shadow of x: row = 16 uint2 = 128 B

__global__ void zero_counts_kernel() {
    int i = blockIdx.x * blockDim.x + threadIdx.x;
    if (i < NN) g_count[i] = 0;
}

// 4 edges per thread (int4 load), RED histogram; also converts x -> fp16 shadow
// via a second index range folded into the same launch (saves a pass).
__global__ void hist_prep_kernel(const int* __restrict__ edge_row,
                                 const float* __restrict__ x) {
    int t = blockIdx.x * blockDim.x + threadIdx.x;
    // --- histogram: threads [0, NE/4) ---
    if (t < NE / 4) {
        int4 r = __ldg(reinterpret_cast<const int4*>(edge_row) + t);
        atomicAdd(&g_count[r.x], 1);
        atomicAdd(&g_count[r.y], 1);
        atomicAdd(&g_count[r.z], 1);
        atomicAdd(&g_count[r.w], 1);
    }
    // --- fp16 shadow: threads [NE/4, NE/4 + NN*16) handle one float4 each ---
    int j = t - NE / 4;
    if (j >= 0 && j < NN * 16) {
        float4 xf = reinterpret_cast<const float4*>(x)[j];
        __half2 h0 = __floats2half2_rn(xf.x, xf.y);
        __half2 h1 = __floats2half2_rn(xf.z, xf.w);
        uint2 packed;
        packed.x = *reinterpret_cast<uint32_t*>(&h0);
        packed.y = *reinterpret_cast<uint32_t*>(&h1);
        g_xh[j] = packed;
    }
}

// Single-block exclusive scan over 65536 counts (1024 threads x 64 each).
__global__ void scan_kernel() {
    __shared__ int partial[1024];
    int t = threadIdx.x;
    int base = t * 64;
    int s = 0;
    #pragma unroll
    for (int i = 0; i < 64; i++) s += g_count[base + i];
    partial[t] = s;
    __syncthreads();
    for (int off = 1; off < 1024; off <<= 1) {
        int v = (t >= off) ? partial[t - off] : 0;
        __syncthreads();
        partial[t] += v;
        __syncthreads();
    }
    int run = (t == 0) ? 0 : partial[t - 1];
    for (int i = 0; i < 64; i++) {
        g_offset[base + i] = run;
        g_cursor[base + i] = run;
        run += g_count[base + i];
    }
    if (t == 1023) g_offset[NN] = run;
}

// Build row-grouped edge records; 4 edges/thread so the 4 atomic-return +
// dependent-store chains overlap (MLP=4).
__global__ void build_kernel(const int* __restrict__ edge_row,
                             const int* __restrict__ edge_col,
                             const float* __restrict__ edge_val) {
    int t = blockIdx.x * blockDim.x + threadIdx.x;
    if (t >= NE / 4) return;
    int4   r = __ldg(reinterpret_cast<const int4*>(edge_row) + t);
    int4   c = __ldg(reinterpret_cast<const int4*>(edge_col) + t);
    float4 v = __ldg(reinterpret_cast<const float4*>(edge_val) + t);

    int p0 = atomicAdd(&g_cursor[r.x], 1);
    int p1 = atomicAdd(&g_cursor[r.y], 1);
    int p2 = atomicAdd(&g_cursor[r.z], 1);
    int p3 = atomicAdd(&g_cursor[r.w], 1);
    g_ecv[p0] = make_int2(c.x, __float_as_int(v.x));
    g_ecv[p1] = make_int2(c.y, __float_as_int(v.y));
    g_ecv[p2] = make_int2(c.z, __float_as_int(v.z));
    g_ecv[p3] = make_int2(c.w, __float_as_int(v.w));
}

// Deterministic gather: 16 lanes per node, each lane owns 4 features.
// Inner loop processes 4 edges per iteration with independent loads (MLP>=8).
// Epilogue fuses + x_0 + bias; out written exactly once, zero atomics.
__global__ void gather_kernel(const float* __restrict__ x0,
                              const float* __restrict__ bias,
                              float* __restrict__ out) {
    int tid  = blockIdx.x * blockDim.x + threadIdx.x;
    int node = tid >> 4;
    int lane = tid & 15;
    if (node >= NN) return;

    int start = g_offset[node];
    int end   = g_offset[node + 1];

    float4 acc = make_float4(0.f, 0.f, 0.f, 0.f);

    int e = start;
    for (; e + 4 <= end; e += 4) {
        // 4 independent edge records (8B each, broadcast across the 16 lanes)
        int2 c0 = __ldg(&g_ecv[e + 0]);
        int2 c1 = __ldg(&g_ecv[e + 1]);
        int2 c2 = __ldg(&g_ecv[e + 2]);
        int2 c3 = __ldg(&g_ecv[e + 3]);
        // 4 independent fp16 gathers
        uint2 p0 = __ldg(&g_xh[(size_t)c0.x * 16 + lane]);
        uint2 p1 = __ldg(&g_xh[(size_t)c1.x * 16 + lane]);
        uint2 p2 = __ldg(&g_xh[(size_t)c2.x * 16 + lane]);
        uint2 p3 = __ldg(&g_xh[(size_t)c3.x * 16 + lane]);

        float v0 = __int_as_float(c0.y), v1 = __int_as_float(c1.y);
        float v2 = __int_as_float(c2.y), v3 = __int_as_float(c3.y);

        float2 a, b;
        a = __half22float2(*reinterpret_cast<__half2*>(&p0.x));
        b = __half22float2(*reinterpret_cast<__half2*>(&p0.y));
        acc.x += v0 * a.x; acc.y += v0 * a.y; acc.z += v0 * b.x; acc.w += v0 * b.y;
        a = __half22float2(*reinterpret_cast<__half2*>(&p1.x));
        b = __half22float2(*reinterpret_cast<__half2*>(&p1.y));
        acc.x += v1 * a.x; acc.y += v1 * a.y; acc.z += v1 * b.x; acc.w += v1 * b.y;
        a = __half22float2(*reinterpret_cast<__half2*>(&p2.x));
        b = __half22float2(*reinterpret_cast<__half2*>(&p2.y));
        acc.x += v2 * a.x; acc.y += v2 * a.y; acc.z += v2 * b.x; acc.w += v2 * b.y;
        a = __half22float2(*reinterpret_cast<__half2*>(&p3.x));
        b = __half22float2(*reinterpret_cast<__half2*>(&p3.y));
        acc.x += v3 * a.x; acc.y += v3 * a.y; acc.z += v3 * b.x; acc.w += v3 * b.y;
    }
    for (; e < end; e++) {
        int2 cv = __ldg(&g_ecv[e]);
        uint2 p = __ldg(&g_xh[(size_t)cv.x * 16 + lane]);
        float v = __int_as_float(cv.y);
        float2 a = __half22float2(*reinterpret_cast<__half2*>(&p.x));
        float2 b = __half22float2(*reinterpret_cast<__half2*>(&p.y));
        acc.x += v * a.x; acc.y += v * a.y; acc.z += v * b.x; acc.w += v * b.y;
    }

    float4 bb = reinterpret_cast<const float4*>(bias)[lane];
    float4 z  = reinterpret_cast<const float4*>(x0)[(size_t)node * 16 + lane];
    float4 o;
    o.x = acc.x + z.x + bb.x;
    o.y = acc.y + z.y + bb.y;
    o.z = acc.z + z.z + bb.z;
    o.w = acc.w + z.w + bb.w;
    reinterpret_cast<float4*>(out)[(size_t)node * 16 + lane] = o;
}

extern "C" void kernel_launch(void* const* d_in, const int* in_sizes, int n_in,
                              void* d_out, int out_size) {
    // metadata order: x, x_0, edge_val, weight, bias, edge_row, edge_col
    const float* x        = (const float*)d_in[0];
    const float* x_0      = (const float*)d_in[1];
    const float* edge_val = (const float*)d_in[2];
    // d_in[3] = weight: Cayley transform solve(I+s, (I-s)^T)^T == I exactly
    // (s skew-symmetric => (I-s)^T is bitwise I+s), so support == x.
    const float* bias     = (const float*)d_in[4];
    const int*   edge_row = (const int*)d_in[5];
    const int*   edge_col = (const int*)d_in[6];
    float* out = (float*)d_out;

    zero_counts_kernel<<<NN / 256, 256>>>();

    int hist_threads = NE / 4 + NN * 16;   // histogram range + fp16-convert range
    hist_prep_kernel<<<(hist_threads + 255) / 256, 256>>>(edge_row, x);

    scan_kernel<<<1, 1024>>>();

    build_kernel<<<(NE / 4 + 255) / 256, 256>>>(edge_row, edge_col, edge_val);

    gather_kernel<<<(NN * 16) / 256, 256>>>(x_0, bias, out);
}

// round 12
// speedup vs baseline: 4.0970x; 4.0970x over previous
#include <cuda_runtime.h>
#include <cuda_fp16.h>
#include <cstdint>

#define NN 65536
#define NE 1048576
#define DFEAT 64

// Scratch (device globals — allocation is forbidden)
__device__ int   g_count[NN];
__device__ int   g_offset[NN + 1];
__device__ int   g_cursor[NN];
__device__ int   g_blocksum[256];
__device__ int   g_blockoff[256];
__device__ int2  g_ecv[NE];          // row-grouped (col, val_bits)
__device__ uint2 g_xh[NN * 16];      // fp16 shadow of x: row = 16 uint2 = 128 B

__global__ void zero_counts_kernel() {
    int i = blockIdx.x * blockDim.x + threadIdx.x;
    if (i < NN) g_count[i] = 0;
}

// Fused: RED histogram of edge_row (4 edges/thread) + fp16 shadow of x.
__global__ void hist_prep_kernel(const int* __restrict__ edge_row,
                                 const float* __restrict__ x) {
    int t = blockIdx.x * blockDim.x + threadIdx.x;
    if (t < NE / 4) {
        int4 r = __ldg(reinterpret_cast<const int4*>(edge_row) + t);
        atomicAdd(&g_count[r.x], 1);
        atomicAdd(&g_count[r.y], 1);
        atomicAdd(&g_count[r.z], 1);
        atomicAdd(&g_count[r.w], 1);
    }
    int j = t - NE / 4;
    if (j >= 0 && j < NN * 16) {
        float4 xf = reinterpret_cast<const float4*>(x)[j];
        __half2 h0 = __floats2half2_rn(xf.x, xf.y);
        __half2 h1 = __floats2half2_rn(xf.z, xf.w);
        uint2 packed;
        packed.x = *reinterpret_cast<uint32_t*>(&h0);
        packed.y = *reinterpret_cast<uint32_t*>(&h1);
        g_xh[j] = packed;
    }
}

// ---- Coalesced 3-phase scan (replaces the 1-block strided scan) ----

// Phase 1: per-chunk sums. 256 blocks x 256 threads, fully coalesced.
__global__ void scan1_kernel() {
    __shared__ int wsum[8];
    int tid = threadIdx.x;
    int v = g_count[blockIdx.x * 256 + tid];
    // warp reduce
    #pragma unroll
    for (int o = 16; o > 0; o >>= 1) v += __shfl_down_sync(0xffffffffu, v, o);
    if ((tid & 31) == 0) wsum[tid >> 5] = v;
    __syncthreads();
    if (tid == 0) {
        int s = 0;
        #pragma unroll
        for (int w = 0; w < 8; w++) s += wsum[w];
        g_blocksum[blockIdx.x] = s;
    }
}

// Phase 2: exclusive scan of 256 block sums (1 block, shared-memory scan).
__global__ void scan2_kernel() {
    __shared__ int sh[256];
    int t = threadIdx.x;
    sh[t] = g_blocksum[t];
    __syncthreads();
    for (int off = 1; off < 256; off <<= 1) {
        int v = (t >= off) ? sh[t - off] : 0;
        __syncthreads();
        sh[t] += v;
        __syncthreads();
    }
    g_blockoff[t] = (t == 0) ? 0 : sh[t - 1];
}

// Phase 3: block-exclusive scan + block offset -> g_offset/g_cursor (coalesced).
__global__ void scan3_kernel() {
    __shared__ int wpref[8];
    int tid  = threadIdx.x;
    int lane = tid & 31;
    int wid  = tid >> 5;
    int i = blockIdx.x * 256 + tid;
    int v = g_count[i];

    // warp inclusive scan
    int incl = v;
    #pragma unroll
    for (int o = 1; o < 32; o <<= 1) {
        int n = __shfl_up_sync(0xffffffffu, incl, o);
        if (lane >= o) incl += n;
    }
    if (lane == 31) wpref[wid] = incl;
    __syncthreads();
    if (wid == 0 && lane < 8) {
        int w = wpref[lane];
        #pragma unroll
        for (int o = 1; o < 8; o <<= 1) {
            int n = __shfl_up_sync(0xffu, w, o);
            if (lane >= o) w += n;
        }
        wpref[lane] = w;
    }
    __syncthreads();
    int excl = incl - v + (wid ? wpref[wid - 1] : 0) + g_blockoff[blockIdx.x];

    g_offset[i] = excl;
    g_cursor[i] = excl;
    if (i == NN - 1) g_offset[NN] = excl + v;
}

// Build row-grouped edge records; 4 edges/thread (overlapped atomic chains).
__global__ void build_kernel(const int* __restrict__ edge_row,
                             const int* __restrict__ edge_col,
                             const float* __restrict__ edge_val) {
    int t = blockIdx.x * blockDim.x + threadIdx.x;
    if (t >= NE / 4) return;
    int4   r = __ldg(reinterpret_cast<const int4*>(edge_row) + t);
    int4   c = __ldg(reinterpret_cast<const int4*>(edge_col) + t);
    float4 v = __ldg(reinterpret_cast<const float4*>(edge_val) + t);

    int p0 = atomicAdd(&g_cursor[r.x], 1);
    int p1 = atomicAdd(&g_cursor[r.y], 1);
    int p2 = atomicAdd(&g_cursor[r.z], 1);
    int p3 = atomicAdd(&g_cursor[r.w], 1);
    g_ecv[p0] = make_int2(c.x, __float_as_int(v.x));
    g_ecv[p1] = make_int2(c.y, __float_as_int(v.y));
    g_ecv[p2] = make_int2(c.z, __float_as_int(v.z));
    g_ecv[p3] = make_int2(c.w, __float_as_int(v.w));
}

// Deterministic gather: 16 lanes per node, lane owns 4 features; 4 edges/iter
// with independent loads. Fused + x_0 + bias epilogue; zero atomics.
__global__ void gather_kernel(const float* __restrict__ x0,
                              const float* __restrict__ bias,
                              float* __restrict__ out) {
    int tid  = blockIdx.x * blockDim.x + threadIdx.x;
    int node = tid >> 4;
    int lane = tid & 15;
    if (node >= NN) return;

    int start = g_offset[node];
    int end   = g_offset[node + 1];

    float4 acc = make_float4(0.f, 0.f, 0.f, 0.f);

    int e = start;
    for (; e + 4 <= end; e += 4) {
        int2 c0 = __ldg(&g_ecv[e + 0]);
        int2 c1 = __ldg(&g_ecv[e + 1]);
        int2 c2 = __ldg(&g_ecv[e + 2]);
        int2 c3 = __ldg(&g_ecv[e + 3]);
        uint2 p0 = __ldg(&g_xh[(size_t)c0.x * 16 + lane]);
        uint2 p1 = __ldg(&g_xh[(size_t)c1.x * 16 + lane]);
        uint2 p2 = __ldg(&g_xh[(size_t)c2.x * 16 + lane]);
        uint2 p3 = __ldg(&g_xh[(size_t)c3.x * 16 + lane]);

        float v0 = __int_as_float(c0.y), v1 = __int_as_float(c1.y);
        float v2 = __int_as_float(c2.y), v3 = __int_as_float(c3.y);

        float2 a, b;
        a = __half22float2(*reinterpret_cast<__half2*>(&p0.x));
        b = __half22float2(*reinterpret_cast<__half2*>(&p0.y));
        acc.x += v0 * a.x; acc.y += v0 * a.y; acc.z += v0 * b.x; acc.w += v0 * b.y;
        a = __half22float2(*reinterpret_cast<__half2*>(&p1.x));
        b = __half22float2(*reinterpret_cast<__half2*>(&p1.y));
        acc.x += v1 * a.x; acc.y += v1 * a.y; acc.z += v1 * b.x; acc.w += v1 * b.y;
        a = __half22float2(*reinterpret_cast<__half2*>(&p2.x));
        b = __half22float2(*reinterpret_cast<__half2*>(&p2.y));
        acc.x += v2 * a.x; acc.y += v2 * a.y; acc.z += v2 * b.x; acc.w += v2 * b.y;
        a = __half22float2(*reinterpret_cast<__half2*>(&p3.x));
        b = __half22float2(*reinterpret_cast<__half2*>(&p3.y));
        acc.x += v3 * a.x; acc.y += v3 * a.y; acc.z += v3 * b.x; acc.w += v3 * b.y;
    }
    for (; e < end; e++) {
        int2 cv = __ldg(&g_ecv[e]);
        uint2 p = __ldg(&g_xh[(size_t)cv.x * 16 + lane]);
        float v = __int_as_float(cv.y);
        float2 a = __half22float2(*reinterpret_cast<__half2*>(&p.x));
        float2 b = __half22float2(*reinterpret_cast<__half2*>(&p.y));
        acc.x += v * a.x; acc.y += v * a.y; acc.z += v * b.x; acc.w += v * b.y;
    }

    float4 bb = reinterpret_cast<const float4*>(bias)[lane];
    float4 z  = reinterpret_cast<const float4*>(x0)[(size_t)node * 16 + lane];
    float4 o;
    o.x = acc.x + z.x + bb.x;
    o.y = acc.y + z.y + bb.y;
    o.z = acc.z + z.z + bb.z;
    o.w = acc.w + z.w + bb.w;
    reinterpret_cast<float4*>(out)[(size_t)node * 16 + lane] = o;
}

extern "C" void kernel_launch(void* const* d_in, const int* in_sizes, int n_in,
                              void* d_out, int out_size) {
    // metadata order: x, x_0, edge_val, weight, bias, edge_row, edge_col
    const float* x        = (const float*)d_in[0];
    const float* x_0      = (const float*)d_in[1];
    const float* edge_val = (const float*)d_in[2];
    // d_in[3] = weight: Cayley transform solve(I+s, (I-s)^T)^T == I exactly
    // (s skew-symmetric => (I-s)^T is bitwise I+s), so support == x.
    const float* bias     = (const float*)d_in[4];
    const int*   edge_row = (const int*)d_in[5];
    const int*   edge_col = (const int*)d_in[6];
    float* out = (float*)d_out;

    zero_counts_kernel<<<NN / 256, 256>>>();

    int hist_threads = NE / 4 + NN * 16;
    hist_prep_kernel<<<(hist_threads + 255) / 256, 256>>>(edge_row, x);

    scan1_kernel<<<256, 256>>>();
    scan2_kernel<<<1, 256>>>();
    scan3_kernel<<<256, 256>>>();

    build_kernel<<<(NE / 4 + 255) / 256, 256>>>(edge_row, edge_col, edge_val);

    gather_kernel<<<(NN * 16) / 256, 256>>>(x_0, bias, out);
}